// round 17
// baseline (speedup 1.0000x reference)
#include <cuda_runtime.h>
#include <math.h>

#define B 1024
#define D 64
#define O 64
#define M 1024
#define DELTA_F 0.13533528323661270f   // exp(-2)

// ------------------------- device scratch (no mallocs) -------------------------
__device__ float g_sen[B];          // ||x_i||^2
__device__ float g_gterm;           // gsm - sum(gm^2)
__device__ int   g_flag;            // 1 => fast-path hypothesis violated -> fallback
__device__ int   g_min_bits = 0x7f800000;  // +inf; min off-diag SUBSPACE d^2
                                           // (int-compare valid: values >= 0).
                                           // Consumed then reset by k_decide each
                                           // call => graph replays see +inf again.
__device__ float g_protos[M * D];
__device__ float g_cents [M * D];
__device__ float g_senc[M];
__device__ float g_cc[M];           // sum(cents^2) per rule
__device__ float g_pp[M];           // sum(protos^2) per rule
__device__ int   g_sup[M];
__device__ int   g_n;
__device__ float g_Gt[B * M];       // fallback only: Gt[i*M + j] = dot(protos_j, x_i)

// ------------------------- K1: fused everything-independent kernel --------------
// Block b (256 threads):
//   * all blocks: y_n for row b, then UNCONDITIONAL identity-pattern row store
//     (zeros + diag y_n). Valid for the fast path; fallback rewrites every byte.
//   * blocks 0..527: 32-dim-projection verify tile -> atomicMin(g_min_bits, d2_S).
//     d2_S(i,j) <= d2(i,j), so min_S above threshold certifies full-dim condition.
//   * block 1023: sen for all rows + g_term.
// Later, k_decide checks: min d2_S > 64|g_term| = 128*stau  =>
//   * d2 > 2*stau => reference scan creates a rule at every step
//     (stau_j = |g_term|/2 exactly in the all-create state: senc_j == cc_j bitwise)
//   * d2 > 128*stau => off-diag reference dens has arg <= -128; expf(-128) ~ 2.6e-56
//     < min fp32 subnormal => dens is BITWISE 0.0f => reference lambda == identity
//     exactly (dens_ii/dens_ii == 1.0f) => the identity pattern emitted here is
//     bitwise-correct.
__global__ void __launch_bounds__(256) k_main(const float* __restrict__ x,
                                              const float* __restrict__ W,
                                              const float* __restrict__ bb,
                                              float4* __restrict__ out) {
    __shared__ float4 xi[32][8];
    __shared__ float4 xj[32][8];
    __shared__ float sni[32], snj[32];
    __shared__ float ynp[4][64];
    __shared__ __align__(16) float yn_f[64];
    __shared__ __align__(16) float xs[64];
    __shared__ float part[4][64];
    __shared__ float sred[8];
    __shared__ float gsq[64];
    int b = blockIdx.x, t = threadIdx.x;
    const float4* xv = reinterpret_cast<const float4*>(x);

    if (t < 64) xs[t] = x[b * D + t];
    __syncthreads();
    // --- y_n partials for row b (all 256 threads, 4 per output) ---
    {
        int o = t & 63, q = t >> 6;
        const float4* Wv = reinterpret_cast<const float4*>(W);
        const float4* xv4 = reinterpret_cast<const float4*>(xs);
        float z = 0.f;
        #pragma unroll
        for (int m = 0; m < 4; m++) {
            float4 w4 = Wv[o * 16 + q * 4 + m];
            float4 xx = xv4[q * 4 + m];
            z += w4.x * xx.x + w4.y * xx.y + w4.z * xx.z + w4.w * xx.w;
        }
        ynp[q][o] = z;
    }
    // --- extra duty: verify tile (blocks 0..527) ---
    if (b < 528) {
        int rem = b, by = 0;
        while (rem >= 32 - by) { rem -= 32 - by; by++; }
        int bx = by + rem;
        int i0 = by * 32, j0 = bx * 32;
        int tx = t & 15, ty = t >> 4;
        {
            int r = t >> 3, c = t & 7;
            xi[r][c ^ (r & 7)] = xv[(i0 + r) * 16 + c];
            xj[r][c ^ (r & 7)] = xv[(j0 + r) * 16 + c];
        }
        __syncthreads();
        if (t < 32) {
            float s = 0.f;
            #pragma unroll
            for (int c = 0; c < 8; c++) { float4 v = xi[t][c]; s += v.x*v.x + v.y*v.y + v.z*v.z + v.w*v.w; }
            sni[t] = s;
        } else if (t < 64) {
            int r = t - 32;
            float s = 0.f;
            #pragma unroll
            for (int c = 0; c < 8; c++) { float4 v = xj[r][c]; s += v.x*v.x + v.y*v.y + v.z*v.z + v.w*v.w; }
            snj[r] = s;
        }
        __syncthreads();
        float a00 = 0.f, a01 = 0.f, a10 = 0.f, a11 = 0.f;
        #pragma unroll
        for (int d4 = 0; d4 < 8; d4++) {
            float4 a0 = xi[ty][d4 ^ (ty & 7)];
            float4 a1 = xi[ty + 16][d4 ^ (ty & 7)];
            float4 b0 = xj[tx][d4 ^ (tx & 7)];
            float4 b1 = xj[tx + 16][d4 ^ (tx & 7)];
            a00 += a0.x * b0.x + a0.y * b0.y + a0.z * b0.z + a0.w * b0.w;
            a01 += a0.x * b1.x + a0.y * b1.y + a0.z * b1.z + a0.w * b1.w;
            a10 += a1.x * b0.x + a1.y * b0.y + a1.z * b0.z + a1.w * b0.w;
            a11 += a1.x * b1.x + a1.y * b1.y + a1.z * b1.z + a1.w * b1.w;
        }
        int ia = i0 + ty, ib = i0 + ty + 16;
        int ja = j0 + tx, jb = j0 + tx + 16;
        float sia = sni[ty], sib = sni[ty + 16];
        float sja = snj[tx], sjb = snj[tx + 16];
        float m = 3.402823466e+38f;
        if (ia != ja) m = fminf(m, sia + sja - 2.0f * a00);
        if (ia != jb) m = fminf(m, sia + sjb - 2.0f * a01);
        if (ib != ja) m = fminf(m, sib + sja - 2.0f * a10);
        if (ib != jb) m = fminf(m, sib + sjb - 2.0f * a11);
        m = fmaxf(m, 0.0f);
        #pragma unroll
        for (int o = 16; o > 0; o >>= 1) m = fminf(m, __shfl_down_sync(0xffffffffu, m, o));
        if ((t & 31) == 0) atomicMin(&g_min_bits, __float_as_int(m));
    } else if (b == 1023) {
        // --- extra duty: sen for all rows + g_term ---
        float senSum = 0.f;
        for (int r = t; r < B; r += 256) {
            const float4* xr = xv + r * 16;
            float s = 0.f;
            #pragma unroll
            for (int m = 0; m < 16; m++) {
                float4 v = xr[m];
                s += v.x * v.x + v.y * v.y + v.z * v.z + v.w * v.w;
            }
            g_sen[r] = s;
            senSum += s;
        }
        #pragma unroll
        for (int o = 16; o > 0; o >>= 1) senSum += __shfl_down_sync(0xffffffffu, senSum, o);
        if ((t & 31) == 0) sred[t >> 5] = senSum;
        // column sums: 4 groups of 256 rows, 64 cols
        int d = t & 63, grp = t >> 6;
        float cs = 0.f;
        for (int r = grp * 256; r < grp * 256 + 256; r++) cs += x[r * D + d];
        part[grp][d] = cs;
        __syncthreads();
        if (t < 64) {
            float tot = part[0][t] + part[1][t] + part[2][t] + part[3][t];
            float gm = tot / 1048576.0f;
            gsq[t] = gm * gm;
        }
        __syncthreads();
        if (t == 0) {
            float sq = 0.f;
            for (int dd = 0; dd < 64; dd++) sq += gsq[dd];
            float ssum = 0.f;
            for (int w = 0; w < 8; w++) ssum += sred[w];
            g_gterm = ssum / 1048576.0f - sq;
        }
    }
    __syncthreads();
    if (t >= 64 && t < 128) {
        int o = t - 64;
        float z = ynp[0][o] + ynp[1][o] + ynp[2][o] + ynp[3][o] + bb[o];
        yn_f[o] = 1.0f / (1.0f + expf(-z));
    }
    __syncthreads();
    // --- unconditional identity-pattern row store ---
    const float4* yn4 = reinterpret_cast<const float4*>(yn_f);
    float4 base = yn4[t & 15];
    float4* dst = out + (size_t)b * 16384 + t;
    int r0 = t >> 4;
    float4 z4 = make_float4(0.f, 0.f, 0.f, 0.f);
    int hit = (r0 == (b & 15)) ? (b >> 4) : -1;
    #pragma unroll
    for (int k = 0; k < 64; k++) {
        float4 v = (k == hit) ? base : z4;
        __stcs(dst + 256 * k, v);            // streaming store: write-once data
    }
}

// ------------------------- K2: flag decision + inline fallback scan -------------
__global__ void __launch_bounds__(1024, 1) k_decide(const float* __restrict__ x) {
    __shared__ int s_flag;
    int t = threadIdx.x;
    if (t == 0) {
        float mind2 = __int_as_float(g_min_bits);
        int flag = (mind2 < 64.0f * fabsf(g_gterm)) ? 1 : 0;
        g_flag = flag;
        s_flag = flag;
        g_min_bits = 0x7f800000;   // reset for next graph replay
    }
    __syncthreads();
    if (s_flag == 0) return;
    // ---------------- exact sequential scan (fallback) ----------------
    __shared__ float xs[64];
    __shared__ float red_val[32];
    __shared__ int   red_idx[32];
    __shared__ int s_n, s_w, s_create;
    __shared__ float s_sf;
    if (t == 0) s_n = 0;
    __syncthreads();
    float gterm = g_gterm;
    for (int i = 0; i < B; i++) {
        if (t < 64) xs[t] = x[i * D + t];
        __syncthreads();
        int n = s_n;
        float dens;
        if (t < n) {
            float dist = 0.f;
            #pragma unroll 8
            for (int dd = 0; dd < 64; dd++) { float v = xs[dd] - g_protos[t * D + dd]; dist += v * v; }
            float stau = fabsf(gterm + g_senc[t] - g_cc[t]) * 0.5f;
            dens = expf(-dist / stau);
        } else dens = -INFINITY;
        float v = dens; int idx = t;
        #pragma unroll
        for (int o = 16; o > 0; o >>= 1) {
            float ov = __shfl_down_sync(0xffffffffu, v, o);
            int   oi = __shfl_down_sync(0xffffffffu, idx, o);
            if (ov > v || (ov == v && oi < idx)) { v = ov; idx = oi; }
        }
        if ((t & 31) == 0) { red_val[t >> 5] = v; red_idx[t >> 5] = idx; }
        __syncthreads();
        if (t < 32) {
            v = red_val[t]; idx = red_idx[t];
            #pragma unroll
            for (int o = 16; o > 0; o >>= 1) {
                float ov = __shfl_down_sync(0xffffffffu, v, o);
                int   oi = __shfl_down_sync(0xffffffffu, idx, o);
                if (ov > v || (ov == v && oi < idx)) { v = ov; idx = oi; }
            }
            if (t == 0) {
                int create = (n == 0) || (v < DELTA_F);
                int w = create ? min(n, M - 1) : idx;
                int supn = create ? 1 : (g_sup[w] + 1);
                g_sup[w] = supn;
                s_w = w; s_create = create; s_sf = (float)supn;
                if (create) s_n = min(n + 1, M);
            }
        }
        __syncthreads();
        int w = s_w; float sf = s_sf; int create = s_create;
        if (t < 64) {
            float xiv = xs[t];
            float p = create ? 0.f : g_protos[w * D + t];
            float c = create ? 0.f : g_cents[w * D + t];
            g_protos[w * D + t] = create ? xiv : p;
            g_cents [w * D + t] = create ? xiv : (c + (xiv - c) / sf);
        }
        __syncthreads();
        if (t < 32) {
            float a = g_cents[w * D + t], b2 = g_cents[w * D + t + 32];
            float s2 = a * a + b2 * b2;
            #pragma unroll
            for (int o = 16; o > 0; o >>= 1) s2 += __shfl_down_sync(0xffffffffu, s2, o);
            if (t == 0) {
                float si = g_sen[i];
                float sc = create ? 0.f : g_senc[w];
                g_senc[w] = create ? si : (sc + (si - sc) / sf);
                g_cc[w] = s2;
            }
        }
        __syncthreads();
    }
    if (t == 0) g_n = s_n;
    __syncthreads();
    // recompute pp and Gt from final protos (slow; only on fallback)
    for (int j = t; j < M; j += 1024) {
        float s2 = 0.f;
        for (int dd = 0; dd < 64; dd++) { float p = g_protos[j * D + dd]; s2 += p * p; }
        g_pp[j] = s2;
    }
    for (int k = t; k < B * M; k += 1024) {
        int i = k >> 10, j = k & (M - 1);
        float s2 = 0.f;
        for (int dd = 0; dd < 64; dd++) s2 += g_protos[j * D + dd] * x[i * D + dd];
        g_Gt[k] = s2;
    }
}

// ------------------------- K3: fallback row rewrite (no-op on fast path) --------
__global__ void __launch_bounds__(256) k_fix(const float* __restrict__ x,
                                             const float* __restrict__ W,
                                             const float* __restrict__ bb,
                                             float4* __restrict__ out) {
    if (g_flag == 0) return;
    __shared__ float lam_s[1024];
    __shared__ float ynp[4][64];
    __shared__ __align__(16) float yn_f[64];
    __shared__ __align__(16) float xs[64];
    __shared__ float red[8];
    __shared__ float s_inv;
    int i = blockIdx.x, t = threadIdx.x;
    if (t < 64) xs[t] = x[i * D + t];
    __syncthreads();
    {
        int o = t & 63, q = t >> 6;
        const float4* Wv = reinterpret_cast<const float4*>(W);
        const float4* xv4 = reinterpret_cast<const float4*>(xs);
        float z = 0.f;
        #pragma unroll
        for (int m = 0; m < 4; m++) {
            float4 w4 = Wv[o * 16 + q * 4 + m];
            float4 xx = xv4[q * 4 + m];
            z += w4.x * xx.x + w4.y * xx.y + w4.z * xx.z + w4.w * xx.w;
        }
        ynp[q][o] = z;
    }
    float dv[4];
    {
        float sen_i = g_sen[i];
        float gterm = g_gterm;
        int n = g_n;
        float local = 0.f;
        #pragma unroll
        for (int k = 0; k < 4; k++) {
            int j = t + k * 256;
            float stau = fabsf(gterm + g_senc[j] - g_cc[j]) * 0.5f;
            float d2 = fmaxf(sen_i + g_pp[j] - 2.0f * g_Gt[i * M + j], 0.0f);
            float arg = -d2 / stau;
            float dens = 0.0f;
            if (j < n && arg > -85.0f) dens = expf(arg);
            dv[k] = dens;
            local += dens;
        }
        #pragma unroll
        for (int o = 16; o > 0; o >>= 1) local += __shfl_down_sync(0xffffffffu, local, o);
        if ((t & 31) == 0) red[t >> 5] = local;
    }
    __syncthreads();
    if (t >= 64 && t < 128) {
        int o = t - 64;
        float z = ynp[0][o] + ynp[1][o] + ynp[2][o] + ynp[3][o] + bb[o];
        yn_f[o] = 1.0f / (1.0f + expf(-z));
    }
    if (t < 8) {
        float v = red[t];
        #pragma unroll
        for (int o = 4; o > 0; o >>= 1) v += __shfl_down_sync(0xffu, v, o);
        if (t == 0) s_inv = 1.0f / v;
    }
    __syncthreads();
    float inv = s_inv;
    #pragma unroll
    for (int k = 0; k < 4; k++) lam_s[t + k * 256] = dv[k] * inv;
    __syncthreads();
    const float4* yn4 = reinterpret_cast<const float4*>(yn_f);
    float4 base = yn4[t & 15];
    float4* dst = out + (size_t)i * 16384 + t;
    int r0 = t >> 4;
    #pragma unroll
    for (int k = 0; k < 64; k++) {
        float l = lam_s[r0 + 16 * k];
        float4 v;
        v.x = base.x * l; v.y = base.y * l; v.z = base.z * l; v.w = base.w * l;
        __stcs(dst + 256 * k, v);
    }
}

// ------------------------- launch -------------------------
extern "C" void kernel_launch(void* const* d_in, const int* in_sizes, int n_in,
                              void* d_out, int out_size) {
    const float* x = (const float*)d_in[0];
    const float* W = (const float*)d_in[1];
    const float* b = (const float*)d_in[2];
    float4* out = (float4*)d_out;

    k_main<<<B, 256>>>(x, W, b, out);
    k_decide<<<1, 1024>>>(x);
    k_fix<<<B, 256>>>(x, W, b, out);
}